// round 17
// baseline (speedup 1.0000x reference)
#include <cuda_runtime.h>
#include <cuda_fp16.h>
#include <stdint.h>

#define VV  128000
#define HH  2048
#define BBS 32
#define SSQ 1024
#define VT  128          // vocab rows per CTA
#define NCTA (VV / VT)   // 1000
#define KCH 64           // K columns per chunk
#define NCH (HH / KCH)   // 32 chunks
#define CAP 4096
#define NBIN 256

// ---------------- scratch (zero at load; k23 re-zeroes g_hist) ----------------
__device__ int   g_hist[BBS * NBIN];
__device__ float g_psumK[NCTA * BBS];

// ---------------- helpers ----------------
__device__ __forceinline__ uint32_t smem_u32(const void* p) {
    uint32_t a;
    asm("{ .reg .u64 t; cvta.to.shared.u64 t, %1; cvt.u32.u64 %0, t; }" : "=r"(a) : "l"(p));
    return a;
}
__device__ __forceinline__ uint32_t pack_f16(float a, float b) {
    __half2 h = __floats2half2_rn(a, b);
    return *(uint32_t*)&h;
}
__device__ __forceinline__ void ldsm_x4(uint32_t* r, uint32_t addr) {
    asm volatile("ldmatrix.sync.aligned.m8n8.x4.shared.b16 {%0,%1,%2,%3}, [%4];"
        : "=r"(r[0]), "=r"(r[1]), "=r"(r[2]), "=r"(r[3]) : "r"(addr));
}
#define MMA(d, a, b0, b1) \
    asm volatile("mma.sync.aligned.m16n8k16.row.col.f32.f16.f16.f32 " \
        "{%0,%1,%2,%3},{%4,%5,%6,%7},{%8,%9},{%0,%1,%2,%3};" \
        : "+f"((d)[0]), "+f"((d)[1]), "+f"((d)[2]), "+f"((d)[3]) \
        : "r"((a)[0]), "r"((a)[1]), "r"((a)[2]), "r"((a)[3]), "r"(b0), "r"(b1))

// fixed-reference bin: logits bounded |l| <= 60
__device__ __forceinline__ int bin_of(float l) {
    int b = (int)((60.0f - l) * 2.0f);
    return b < 0 ? 0 : (b > 255 ? 255 : b);
}

// static smem layout K1: two fp16 stages + temps + warp sums
#define SAS 72                   // row stride in f16 elems (144 B)
#define OA  0
#define OB  18432
#define STG 23040
#define OTM (2 * STG)            // 46080: temps (128 B)
#define OWM (OTM + 128)          // 46208: warp partial sums (1024 B)
#define SMEM_K1 (OWM + 1024)     // 47232 < 48K

// ---------------- K1: fp16 mma GEMM + softcap/temp + hist + sumexp partials ----------------
__global__ __launch_bounds__(256, 2)
void k1_gemm(const float* __restrict__ emb, const float* __restrict__ hid,
             const int* __restrict__ posp, const float* __restrict__ temps,
             float* __restrict__ outL)
{
    __shared__ __align__(16) char smem[SMEM_K1];
    const uint32_t sb = smem_u32(smem);
    const int t = threadIdx.x, wid = t >> 5, l = t & 31;
    const int v0 = blockIdx.x * VT;
    const int pos = posp[0];

    if (t < 32) *(float*)(smem + OTM + t * 4) = temps[t];

    float d[4][4];
    #pragma unroll
    for (int i = 0; i < 4; i++)
        #pragma unroll
        for (int j = 0; j < 4; j++) d[i][j] = 0.f;

    // ldmatrix lane geometry (verified R11..R16)
    const int m0 = wid * 16;
    const int arow = (l < 16) ? l : l - 16;
    const int acol = (l < 16) ? 0 : 8;
    const uint32_t aoff = ((m0 + arow) * SAS + acol) * 2;
    const int brow = (l & 7) + ((l >= 16) ? 8 : 0);
    const int bcol = (l & 8) ? 8 : 0;
    const uint32_t boff0 = (brow * SAS + bcol) * 2;
    const uint32_t boff1 = boff0 + 16 * SAS * 2;

    float4 evA[8], evB[2];
    #pragma unroll
    for (int i = 0; i < 8; i++) {
        int g = i * 256 + t, row = g >> 4, c4 = g & 15;
        evA[i] = *(const float4*)(emb + (size_t)(v0 + row) * HH + c4 * 4);
    }
    #pragma unroll
    for (int i = 0; i < 2; i++) {
        int g = i * 256 + t, row = g >> 4, c4 = g & 15;
        evB[i] = *(const float4*)(hid + ((size_t)row * SSQ + pos) * HH + c4 * 4);
    }

    for (int c = 0; c < NCH; c++) {
        char* stg = smem + (c & 1) * STG;
        const uint32_t sgb = sb + (c & 1) * STG;
        #pragma unroll
        for (int i = 0; i < 8; i++) {
            int g = i * 256 + t, row = g >> 4, c4 = g & 15;
            float4 v = evA[i];
            uint32_t off = row * (SAS * 2) + c4 * 8;
            *(uint2*)(stg + OA + off) = make_uint2(pack_f16(v.x, v.y), pack_f16(v.z, v.w));
        }
        #pragma unroll
        for (int i = 0; i < 2; i++) {
            int g = i * 256 + t, row = g >> 4, c4 = g & 15;
            float4 v = evB[i];
            uint32_t off = row * (SAS * 2) + c4 * 8;
            *(uint2*)(stg + OB + off) = make_uint2(pack_f16(v.x, v.y), pack_f16(v.z, v.w));
        }
        __syncthreads();
        int kn = (c + 1) * KCH;
        if (kn < HH) {
            #pragma unroll
            for (int i = 0; i < 8; i++) {
                int g = i * 256 + t, row = g >> 4, c4 = g & 15;
                evA[i] = *(const float4*)(emb + (size_t)(v0 + row) * HH + kn + c4 * 4);
            }
            #pragma unroll
            for (int i = 0; i < 2; i++) {
                int g = i * 256 + t, row = g >> 4, c4 = g & 15;
                evB[i] = *(const float4*)(hid + ((size_t)row * SSQ + pos) * HH + kn + c4 * 4);
            }
        }
        #pragma unroll
        for (int ks = 0; ks < 4; ks++) {
            uint32_t ko = ks * 32;
            uint32_t aH[4], bH0[4], bH1[4];
            ldsm_x4(aH,  sgb + OA + aoff  + ko);
            ldsm_x4(bH0, sgb + OB + boff0 + ko);
            ldsm_x4(bH1, sgb + OB + boff1 + ko);
            MMA(d[0], aH, bH0[0], bH0[1]);
            MMA(d[1], aH, bH0[2], bH0[3]);
            MMA(d[2], aH, bH1[0], bH1[1]);
            MMA(d[3], aH, bH1[2], bH1[3]);
        }
    }

    // ---- epilogue: softcap + temperature, write logits, hist + sumexp ----
    const int g = l >> 2, tg = l & 3;
    float lv[4][4];   // [nt][{00,10,01,11}]
    #pragma unroll
    for (int nt = 0; nt < 4; nt++) {
        int b0 = nt * 8 + tg * 2;
        float t0 = *(float*)(smem + OTM + b0 * 4);
        float t1 = *(float*)(smem + OTM + (b0 + 1) * 4);
        int vlo = v0 + m0 + g, vhi = vlo + 8;
        lv[nt][0] = tanhf(d[nt][0] / 30.0f) * 30.0f / t0;
        lv[nt][1] = tanhf(d[nt][1] / 30.0f) * 30.0f / t1;
        lv[nt][2] = tanhf(d[nt][2] / 30.0f) * 30.0f / t0;
        lv[nt][3] = tanhf(d[nt][3] / 30.0f) * 30.0f / t1;
        outL[(size_t)b0 * VV + vlo]       = lv[nt][0];
        outL[(size_t)(b0 + 1) * VV + vlo] = lv[nt][1];
        outL[(size_t)b0 * VV + vhi]       = lv[nt][2];
        outL[(size_t)(b0 + 1) * VV + vhi] = lv[nt][3];
    }
    __syncthreads();                       // all MMA smem reads done
    int* shist = (int*)smem;               // reuse stage area: 32*256*4 = 32768 B
    for (int i = t; i < BBS * NBIN; i += 256) shist[i] = 0;
    __syncthreads();

    float es[4][2];
    #pragma unroll
    for (int nt = 0; nt < 4; nt++) {
        int b0 = nt * 8 + tg * 2;
        atomicAdd(&shist[b0 * NBIN + bin_of(lv[nt][0])], 1);
        atomicAdd(&shist[(b0 + 1) * NBIN + bin_of(lv[nt][1])], 1);
        atomicAdd(&shist[b0 * NBIN + bin_of(lv[nt][2])], 1);
        atomicAdd(&shist[(b0 + 1) * NBIN + bin_of(lv[nt][3])], 1);
        es[nt][0] = expf(lv[nt][0]) + expf(lv[nt][2]);
        es[nt][1] = expf(lv[nt][1]) + expf(lv[nt][3]);
    }
    #pragma unroll
    for (int o = 4; o <= 16; o <<= 1)
        #pragma unroll
        for (int nt = 0; nt < 4; nt++) {
            es[nt][0] += __shfl_xor_sync(0xffffffffu, es[nt][0], o);
            es[nt][1] += __shfl_xor_sync(0xffffffffu, es[nt][1], o);
        }
    float* wsum = (float*)(smem + OWM);
    if (l < 4) {
        #pragma unroll
        for (int nt = 0; nt < 4; nt++) {
            wsum[wid * 32 + nt * 8 + l * 2]     = es[nt][0];
            wsum[wid * 32 + nt * 8 + l * 2 + 1] = es[nt][1];
        }
    }
    __syncthreads();
    // merge histogram to global (int atomics, deterministic)
    for (int i = t; i < BBS * NBIN; i += 256) {
        int c = shist[i];
        if (c) atomicAdd(&g_hist[i], c);
    }
    // per-CTA deterministic sum partials
    if (t < 32) {
        float s = 0.f;
        #pragma unroll
        for (int w = 0; w < 8; w++) s += wsum[w * 32 + t];   // fixed order
        g_psumK[blockIdx.x * 32 + t] = s;
    }
}

// ---------------- Threefry-2x32 (JAX partitionable, key(42)) ----------------
__device__ __forceinline__ void tf_round(uint32_t &x0, uint32_t &x1, int r) {
    x0 += x1; x1 = (x1 << r) | (x1 >> (32 - r)); x1 ^= x0;
}
__device__ float gumbel_for(uint32_t n) {
    uint32_t x0 = 0u, x1 = n;
    const uint32_t k0 = 0u, k1 = 42u, k2 = 0x1BD11BDAu ^ k0 ^ k1;
    x0 += k0; x1 += k1;
    tf_round(x0,x1,13); tf_round(x0,x1,15); tf_round(x0,x1,26); tf_round(x0,x1,6);
    x0 += k1; x1 += k2 + 1u;
    tf_round(x0,x1,17); tf_round(x0,x1,29); tf_round(x0,x1,16); tf_round(x0,x1,24);
    x0 += k2; x1 += k0 + 2u;
    tf_round(x0,x1,13); tf_round(x0,x1,15); tf_round(x0,x1,26); tf_round(x0,x1,6);
    x0 += k0; x1 += k1 + 3u;
    tf_round(x0,x1,17); tf_round(x0,x1,29); tf_round(x0,x1,16); tf_round(x0,x1,24);
    x0 += k1; x1 += k2 + 4u;
    tf_round(x0,x1,13); tf_round(x0,x1,15); tf_round(x0,x1,26); tf_round(x0,x1,6);
    x0 += k2; x1 += k0 + 5u;
    uint32_t bits = x0 ^ x1;
    float u = __uint_as_float((bits >> 9) | 0x3f800000u) - 1.0f;
    u = u + 1.17549435e-38f;
    u = fmaxf(1.17549435e-38f, u);
    return -logf(-logf(u));
}

// ---------------- k23: sum+threshold+collect+exact recompute+rank+sample ----------------
__global__ __launch_bounds__(1024)
void k23_sample(const float* __restrict__ outL,
                const float* __restrict__ emb, const float* __restrict__ hid,
                const int* __restrict__ posp, const float* __restrict__ temps,
                const float* __restrict__ tps, const int* __restrict__ tks,
                float* __restrict__ out)
{
    const int b = blockIdx.x, t = threadIdx.x;
    const int wid = t >> 5, lane = t & 31;
    __shared__ __align__(16) float hs[HH];          // 8 KB
    __shared__ float sv[CAP];                        // 16 KB
    __shared__ int   si[CAP];                        // 16 KB
    __shared__ float red[1024];                      // 4 KB
    __shared__ float tv[64];
    __shared__ int   tix[64];
    __shared__ int   s_n, s_bs;
    __shared__ float s_S0;

    // stage hidden row + sum partials
    const int pos = posp[0];
    if (t < 512) ((float4*)hs)[t] = ((const float4*)(hid + ((size_t)b * SSQ + pos) * HH))[t];
    red[t] = (t < NCTA) ? g_psumK[t * 32 + b] : 0.f;
    if (t == 0) s_n = 0;
    __syncthreads();
    #pragma unroll
    for (int s = 512; s > 0; s >>= 1) {
        if (t < s) red[t] += red[t + s];
        __syncthreads();
    }
    if (t == 0) s_S0 = red[0];

    // threshold: smallest bin bs with cumulative count >= 64 (warp 0)
    if (t < 32) {
        int loc[8], s = 0;
        #pragma unroll
        for (int i = 0; i < 8; i++) { loc[i] = g_hist[b * NBIN + t * 8 + i]; s += loc[i]; }
        int inc = s;
        #pragma unroll
        for (int o = 1; o < 32; o <<= 1) {
            int v = __shfl_up_sync(0xffffffffu, inc, o);
            if (lane >= o) inc += v;
        }
        int cum = inc - s, found = NBIN;
        #pragma unroll
        for (int i = 0; i < 8; i++) { cum += loc[i]; if (cum >= 64 && found == NBIN) found = t * 8 + i; }
        #pragma unroll
        for (int o = 16; o; o >>= 1) found = min(found, __shfl_xor_sync(0xffffffffu, found, o));
        if (lane == 0) s_bs = min(found, NBIN - 1);
    }
    __syncthreads();
    const int bs = s_bs;

    // collect candidate indices from this row's logits
    const float4* r4 = (const float4*)(outL + (size_t)b * VV);
    for (int i = t; i < VV / 4; i += 1024) {
        float4 v = r4[i];
        float vals[4] = {v.x, v.y, v.z, v.w};
        #pragma unroll
        for (int j = 0; j < 4; j++) {
            if (bin_of(vals[j]) <= bs) {
                int p = atomicAdd(&s_n, 1);
                if (p < CAP) si[p] = i * 4 + j;
            }
        }
    }
    __syncthreads();
    int n = s_n; if (n > CAP) n = CAP;

    // exact fp32 recompute (one warp per candidate)
    const float temp = temps[b];
    for (int c = wid; c < n; c += 32) {
        const float4* er = (const float4*)(emb + (size_t)si[c] * HH);
        float acc = 0.f;
        #pragma unroll
        for (int j = 0; j < 16; j++) {
            float4 e = er[lane + j * 32];
            float4 h = ((const float4*)hs)[lane + j * 32];
            acc += e.x * h.x + e.y * h.y + e.z * h.z + e.w * h.w;
        }
        #pragma unroll
        for (int o = 16; o; o >>= 1) acc += __shfl_xor_sync(0xffffffffu, acc, o);
        if (lane == 0) sv[c] = tanhf(acc / 30.0f) * 30.0f / temp;
    }
    __syncthreads();

    // rank by exact (value desc, index asc) == stable argsort(-probs)
    for (int j = t; j < n; j += 1024) {
        float v = sv[j]; int id = si[j]; int r = 0;
        for (int i = 0; i < n; i++) {
            float vi = sv[i];
            if (vi > v || (vi == v && si[i] < id)) r++;
        }
        if (r < 64) { tv[r] = v; tix[r] = id; }
    }
    __syncthreads();

    if (t == 0) {
        int m = n < 64 ? n : 64;
        float S0 = s_S0;
        float tp = tps[b]; int kk = tks[b];
        float cum = 0.f, best = __int_as_float(0xff800000);
        int bid = 0;
        for (int j = 0; j < m; j++) {
            float p = expf(tv[j]) / S0;
            cum += p;
            bool keep = !((cum - p) > tp) && (j < kk);
            if (keep) {
                float sc = tv[j] + gumbel_for((uint32_t)(b * VV + tix[j]));
                if (sc > best) { best = sc; bid = tix[j]; }
            }
        }
        out[b] = (float)bid;
    }

    // reset for next graph replay
    __syncthreads();
    if (t < NBIN) g_hist[b * NBIN + t] = 0;
}

// ---------------- launch ----------------
extern "C" void kernel_launch(void* const* d_in, const int* in_sizes, int n_in,
                              void* d_out, int out_size)
{
    const float* emb  = (const float*)d_in[0];
    const float* hid  = (const float*)d_in[1];
    const int*   posp = (const int*)  d_in[2];
    const float* tps  = (const float*)d_in[3];
    const int*   tks  = (const int*)  d_in[4];
    const float* tmps = (const float*)d_in[5];
    float* out  = (float*)d_out;
    float* outL = out + BBS;

    k1_gemm<<<NCTA, 256>>>(emb, hid, posp, tmps, outL);
    k23_sample<<<BBS, 1024>>>(outL, emb, hid, posp, tmps, tps, tks, out);
}